// round 15
// baseline (speedup 1.0000x reference)
#include <cuda_runtime.h>
#include <cuda_fp16.h>
#include <math.h>

#define Bb 64
#define Tt 1024
#define Ii 64
#define Hh 512
#define G3 1536
#define BT (Bb*Tt)
#define NBLK 128
#define BH (Bb*Hh)

// SMEM byte offsets (dynamic smem)
#define OFF_HI   0                       // h plane ring: 64 rows x 520 halves = 66560 B
#define OFF_WF   66560                   // w fragments: 2048 uint2 = 16 KB
#define OFF_PART 82944                   // 64x12 f32 = 3 KB
#define OFF_OWN  86016                   // 64x4 f32 exact h
#define SMEM_TOTAL_B 87040

// ---------------- scratch (static device allocations only) ----------------
__device__ float g_xg[(size_t)BT * G3];
__device__ float g_y[(size_t)BT * Hh];
__device__ __align__(128) __half g_hhi[2 * BH];   // fp16 hidden, ping-pong [b][hidden]
__device__ float g_wih0T[Ii * G3];
__device__ float g_wih1T[Hh * G3];
__device__ float g_fcwT[Hh * Ii];

// hierarchical barrier state (relaxed atomics + fences)
__device__ __align__(128) unsigned int g_sub[8 * 32];   // 8 counters, 128B apart
__device__ unsigned int g_master;
__device__ unsigned int g_gen;

// ---------------- transpose: in[R][C] -> out[C][R] ----------------
__global__ void transpose_k(const float* __restrict__ in, float* __restrict__ out,
                            int R, int C) {
    __shared__ float tile[32][33];
    int c0 = blockIdx.x * 32, r0 = blockIdx.y * 32;
    int x = threadIdx.x, y = threadIdx.y;
#pragma unroll
    for (int j = 0; j < 32; j += 8)
        tile[y + j][x] = in[(size_t)(r0 + y + j) * C + c0 + x];
    __syncthreads();
#pragma unroll
    for (int j = 0; j < 32; j += 8)
        out[(size_t)(c0 + y + j) * R + r0 + x] = tile[x][y + j];
}

// ---------------- tiled GEMM: out[M][N] = X[M][K] @ Wt[K][N] + bias ----------------
__global__ void gemm_bias(const float* __restrict__ X, const float* __restrict__ Wt,
                          const float* __restrict__ bias, float* __restrict__ out,
                          int M, int K, int N) {
    __shared__ float As[16][64];
    __shared__ float Bs[16][64];
    int tid = threadIdx.x;
    int n0 = blockIdx.x * 64, m0 = blockIdx.y * 64;
    int tx = tid % 16, ty = tid / 16;
    int am = tid / 4, ak = (tid % 4) * 4;
    int bk = tid / 16, bn = (tid % 16) * 4;
    float acc[4][4];
#pragma unroll
    for (int i = 0; i < 4; i++)
#pragma unroll
        for (int j = 0; j < 4; j++) acc[i][j] = 0.f;

    for (int k0 = 0; k0 < K; k0 += 16) {
        float4 av = *(const float4*)&X[(size_t)(m0 + am) * K + k0 + ak];
        As[ak + 0][am] = av.x; As[ak + 1][am] = av.y;
        As[ak + 2][am] = av.z; As[ak + 3][am] = av.w;
        *(float4*)&Bs[bk][bn] = *(const float4*)&Wt[(size_t)(k0 + bk) * N + n0 + bn];
        __syncthreads();
#pragma unroll
        for (int k = 0; k < 16; k++) {
            float4 a = *(const float4*)&As[k][ty * 4];
            float4 b = *(const float4*)&Bs[k][tx * 4];
            acc[0][0] += a.x * b.x; acc[0][1] += a.x * b.y; acc[0][2] += a.x * b.z; acc[0][3] += a.x * b.w;
            acc[1][0] += a.y * b.x; acc[1][1] += a.y * b.y; acc[1][2] += a.y * b.z; acc[1][3] += a.y * b.w;
            acc[2][0] += a.z * b.x; acc[2][1] += a.z * b.y; acc[2][2] += a.z * b.z; acc[2][3] += a.z * b.w;
            acc[3][0] += a.w * b.x; acc[3][1] += a.w * b.y; acc[3][2] += a.w * b.z; acc[3][3] += a.w * b.w;
        }
        __syncthreads();
    }
    float4 bv = *(const float4*)&bias[n0 + tx * 4];
#pragma unroll
    for (int i = 0; i < 4; i++) {
        float4 o;
        o.x = acc[i][0] + bv.x; o.y = acc[i][1] + bv.y;
        o.z = acc[i][2] + bv.z; o.w = acc[i][3] + bv.w;
        *(float4*)&out[(size_t)(m0 + ty * 4 + i) * N + n0 + tx * 4] = o;
    }
}

// ---------------- hierarchical grid barrier, relaxed atomics + fences ----------------
__global__ void bar_reset() {
    for (int i = 0; i < 8 * 32; i++) g_sub[i] = 0u;
    g_master = 0u;
    g_gen = 0u;
}

// Monotonic counters. Round `target`: 16 blocks/subgroup -> sub counter reaches
// target*16; 16th arriver bumps master; 8th master arriver publishes g_gen.
// Data visibility via explicit __threadfence on both sides (R9-proven pattern);
// all atomics are plain/relaxed.
__device__ __forceinline__ void grid_barrier(unsigned int target) {
    __syncthreads();
    if (threadIdx.x == 0) {
        __threadfence();   // release this block's h writes
        unsigned int old = atomicAdd(&g_sub[(blockIdx.x & 7) * 32], 1u);
        if (old == target * 16u - 1u) {
            unsigned int mo = atomicAdd(&g_master, 1u);
            if (mo == target * 8u - 1u) {
                atomicExch(&g_gen, target);
            }
        }
        while (*((volatile unsigned int*)&g_gen) < target) {}
        __threadfence();   // acquire side
    }
    __syncthreads();
}

// ---------------- mma / async-copy helpers ----------------
__device__ __forceinline__ void mma16816(float* c, unsigned a0, unsigned a1,
                                         unsigned a2, unsigned a3,
                                         unsigned b0, unsigned b1) {
    asm volatile(
        "mma.sync.aligned.m16n8k16.row.col.f32.f16.f16.f32 "
        "{%0,%1,%2,%3}, {%4,%5,%6,%7}, {%8,%9}, {%0,%1,%2,%3};"
        : "+f"(c[0]), "+f"(c[1]), "+f"(c[2]), "+f"(c[3])
        : "r"(a0), "r"(a1), "r"(a2), "r"(a3), "r"(b0), "r"(b1));
}

__device__ __forceinline__ void ldsm4(unsigned& r0, unsigned& r1, unsigned& r2,
                                      unsigned& r3, unsigned addr) {
    asm volatile("ldmatrix.sync.aligned.m8n8.x4.shared.b16 {%0,%1,%2,%3}, [%4];"
                 : "=r"(r0), "=r"(r1), "=r"(r2), "=r"(r3) : "r"(addr));
}

__device__ __forceinline__ unsigned pack2h(__half a, __half b) {
    return (unsigned)__half_as_ushort(a) | ((unsigned)__half_as_ushort(b) << 16);
}

__device__ __forceinline__ void cpa16(unsigned dst, const void* src) {
    asm volatile("cp.async.cg.shared.global [%0], [%1], 16;" :: "r"(dst), "l"(src));
}
__device__ __forceinline__ void cpa_commit() {
    asm volatile("cp.async.commit_group;" ::: "memory");
}

__device__ __forceinline__ float fsig(float x) {
    return 1.f / (1.f + __expf(-x));
}
__device__ __forceinline__ float ftanh(float x) {
    return 2.f / (1.f + __expf(-2.f * x)) - 1.f;
}

// stage one k-chunk (128 halves of K) of the h plane: 64 rows x 256 B
__device__ __forceinline__ void stage_chunk(unsigned smem_b, const __half* shi,
                                            int c, int tid) {
#pragma unroll
    for (int u = 0; u < 4; u++) {
        int q = tid + u * 256;            // 0..1023
        int m = q >> 4, seg = q & 15;     // 64 rows x 16 segs of 16B
        cpa16(smem_b + OFF_HI + (unsigned)(m * 1040 + c * 256 + seg * 16),
              shi + m * 512 + c * 128 + seg * 8);
    }
}

// ---------------- persistent single-fp16 tensor-core GRU layer ----------------
// 128 blocks x 256 threads (8 warps). Block bid owns h-cols j0..j0+3.
// warp wid: mi = wid>>1 (rows mi*16..+16), ni = wid&1 (cols ni*8..+8 of 12).
__global__ void __launch_bounds__(256, 1)
gru_layer_mma(const float* __restrict__ xg, const float* __restrict__ whh,
              const float* __restrict__ bhh, __half* __restrict__ hhi,
              float* __restrict__ y) {
    extern __shared__ unsigned char smraw[];
    float* part = (float*)(smraw + OFF_PART);
    float* own  = (float*)(smraw + OFF_OWN);
    uint2* wf   = (uint2*)(smraw + OFF_WF);
    const unsigned smem_b = (unsigned)__cvta_generic_to_shared(smraw);

    const int tid = threadIdx.x, bid = blockIdx.x;
    const int j0 = bid * 4;
    const int lane = tid & 31, wid = tid >> 5;
    const int mi = wid >> 1, ni = wid & 1;

    // ---- one-time: W_hh fragments (fp16, mma B-frag order, single plane) ----
    for (int q = tid; q < 2048; q += 256) {
        int l = q & 31, s = (q >> 5) & 31, nn = q >> 10;
        int c = nn * 8 + (l >> 2), t = l & 3;
        float e0 = 0.f, e1 = 0.f, e2 = 0.f, e3 = 0.f;
        if (c < 12) {
            int g = c >> 2, jj = c & 3;
            const float* wr = whh + (size_t)(g * Hh + j0 + jj) * Hh;
            int k = s * 16 + t * 2;
            e0 = wr[k]; e1 = wr[k + 1]; e2 = wr[k + 8]; e3 = wr[k + 9];
        }
        uint2 v;
        v.x = pack2h(__float2half_rn(e0), __float2half_rn(e1));
        v.y = pack2h(__float2half_rn(e2), __float2half_rn(e3));
        wf[q] = v;
    }

    // zero h plane slot 0 + own exact-h
    {
        int i = bid * 256 + tid;   // exactly BH chip-wide
        hhi[i] = __float2half_rn(0.f);
    }
    own[tid] = 0.f;

    // hoisted per-thread constants for the update phase
    const int ub = tid >> 2, uj = tid & 3;
    const float bhr = bhh[j0 + uj];
    const float bhz = bhh[Hh + j0 + uj];
    const float bhn = bhh[2 * Hh + j0 + uj];
    const float* xp = xg + (size_t)ub * Tt * G3 + j0 + uj;
    float* yp = y + (size_t)ub * Tt * Hh + j0 + uj;

    // ldmatrix A address; B frag address
    const unsigned aoff = (unsigned)((mi * 16 + (lane & 15)) * 1040 + (lane >> 4) * 16);
    const unsigned a_hi = smem_b + OFF_HI + aoff;
    const unsigned bbase = smem_b + OFF_WF + (unsigned)(ni * 8192 + lane * 8);

    unsigned int bar = 0;
    grid_barrier(++bar);

    for (int t = 0; t < Tt; t++) {
        const __half* shi = hhi + (t & 1) * BH;
        __half* nhi = hhi + ((t + 1) & 1) * BH;

        // prefetch xg (DRAM) for the gate phase
        float xr = xp[(size_t)t * G3];
        float xz = xp[(size_t)t * G3 + Hh];
        float xn = xp[(size_t)t * G3 + 2 * Hh];

        // ---- pipelined stage + mma over 4 k-chunks (128 halves each) ----
        float acc0[4] = {0.f, 0.f, 0.f, 0.f};
        float acc1[4] = {0.f, 0.f, 0.f, 0.f};

        stage_chunk(smem_b, shi, 0, tid);
        cpa_commit();

#pragma unroll
        for (int c = 0; c < 4; c++) {
            if (c < 3) {
                stage_chunk(smem_b, shi, c + 1, tid);
                cpa_commit();
                asm volatile("cp.async.wait_group 1;" ::: "memory");
            } else {
                asm volatile("cp.async.wait_group 0;" ::: "memory");
            }
            __syncthreads();
#pragma unroll
            for (int sl = 0; sl < 8; sl++) {
                int s = c * 8 + sl;
                unsigned A0, A1, A2, A3;
                ldsm4(A0, A1, A2, A3, a_hi + s * 32);
                unsigned b0, b1;
                asm volatile("ld.shared.v2.u32 {%0,%1}, [%2];"
                             : "=r"(b0), "=r"(b1) : "r"(bbase + s * 256));
                mma16816((sl & 1) ? acc1 : acc0, A0, A1, A2, A3, b0, b1);
            }
        }
        {
            float d0 = acc0[0] + acc1[0];
            float d1 = acc0[1] + acc1[1];
            float d2 = acc0[2] + acc1[2];
            float d3 = acc0[3] + acc1[3];
            int r = lane >> 2, tc = (lane & 3) * 2;
            int b = mi * 16 + r;
            int c0 = ni * 8 + tc;
            if (c0 < 12)     { part[b * 12 + c0]     = d0; part[(b + 8) * 12 + c0]     = d2; }
            if (c0 + 1 < 12) { part[b * 12 + c0 + 1] = d1; part[(b + 8) * 12 + c0 + 1] = d3; }
        }
        __syncthreads();

        // ---- gate update (all 256 threads: (b, j)) ----
        {
            float hr = bhr + part[ub * 12 + uj];
            float hz = bhz + part[ub * 12 + 4 + uj];
            float hn_ = bhn + part[ub * 12 + 8 + uj];
            float r = fsig(xr + hr);
            float z = fsig(xz + hz);
            float n = ftanh(xn + r * hn_);
            float hp = own[ub * 4 + uj];
            float v = (1.f - z) * n + z * hp;
            own[ub * 4 + uj] = v;
            nhi[ub * Hh + j0 + uj] = __float2half_rn(v);
            yp[(size_t)t * Hh] = v;
        }
        grid_barrier(++bar);
    }
}

// ---------------- launch ----------------
extern "C" void kernel_launch(void* const* d_in, const int* in_sizes, int n_in,
                              void* d_out, int out_size) {
    const float* x     = (const float*)d_in[0];
    const float* w_ih0 = (const float*)d_in[1];
    const float* w_hh0 = (const float*)d_in[2];
    const float* b_ih0 = (const float*)d_in[3];
    const float* b_hh0 = (const float*)d_in[4];
    const float* w_ih1 = (const float*)d_in[5];
    const float* w_hh1 = (const float*)d_in[6];
    const float* b_ih1 = (const float*)d_in[7];
    const float* b_hh1 = (const float*)d_in[8];
    const float* fc_w  = (const float*)d_in[9];
    const float* fc_b  = (const float*)d_in[10];
    float* out = (float*)d_out;

    float *xg, *y, *wih0T, *wih1T, *fcwT;
    __half* hhi;
    cudaGetSymbolAddress((void**)&xg,    g_xg);
    cudaGetSymbolAddress((void**)&y,     g_y);
    cudaGetSymbolAddress((void**)&hhi,   g_hhi);
    cudaGetSymbolAddress((void**)&wih0T, g_wih0T);
    cudaGetSymbolAddress((void**)&wih1T, g_wih1T);
    cudaGetSymbolAddress((void**)&fcwT,  g_fcwT);

    cudaFuncSetAttribute(gru_layer_mma,
                         cudaFuncAttributeMaxDynamicSharedMemorySize, SMEM_TOTAL_B);

    dim3 tb(32, 8);
    transpose_k<<<dim3(Ii / 32, G3 / 32), tb>>>(w_ih0, wih0T, G3, Ii);
    transpose_k<<<dim3(Hh / 32, G3 / 32), tb>>>(w_ih1, wih1T, G3, Hh);
    transpose_k<<<dim3(Hh / 32, Ii / 32), tb>>>(fc_w,  fcwT,  Ii, Hh);

    // -------- layer 0 --------
    gemm_bias<<<dim3(G3 / 64, BT / 64), 256>>>(x, wih0T, b_ih0, xg, BT, Ii, G3);
    bar_reset<<<1, 1>>>();
    gru_layer_mma<<<NBLK, 256, SMEM_TOTAL_B>>>(xg, w_hh0, b_hh0, hhi, y);

    // -------- layer 1 --------
    gemm_bias<<<dim3(G3 / 64, BT / 64), 256>>>(y, wih1T, b_ih1, xg, BT, Hh, G3);
    bar_reset<<<1, 1>>>();
    gru_layer_mma<<<NBLK, 256, SMEM_TOTAL_B>>>(xg, w_hh1, b_hh1, hhi, y);

    // -------- final FC --------
    gemm_bias<<<dim3(Ii / 64, BT / 64), 256>>>(y, fcwT, fc_b, out, BT, Hh, Ii);
}

// round 16
// speedup vs baseline: 1.1985x; 1.1985x over previous
#include <cuda_runtime.h>
#include <cuda_fp16.h>
#include <math.h>

#define Bb 64
#define Tt 1024
#define Ii 64
#define Hh 512
#define G3 1536
#define BT (Bb*Tt)
#define NBLK 128
#define BH (Bb*Hh)

// SMEM byte offsets (dynamic smem)
#define OFF_HI   0                       // h plane ring: 64 rows x 520 halves = 66560 B
#define OFF_WF   66560                   // w fragments: 2048 uint2 = 16 KB
#define OFF_PART 82944                   // 64x12 f32 = 3 KB
#define OFF_OWN  86016                   // 64x4 f32 exact h
#define SMEM_TOTAL_B 87040

// ---------------- scratch (static device allocations only) ----------------
__device__ float g_xg[(size_t)BT * G3];
__device__ float g_y[(size_t)BT * Hh];
__device__ __align__(128) __half g_hhi[2 * BH];   // fp16 hidden, ping-pong [b][hidden]
__device__ float g_wih0T[Ii * G3];
__device__ float g_wih1T[Hh * G3];
__device__ float g_fcwT[Hh * Ii];

// dataflow sync: 4 per-group monotonic counters (128B apart) + init barrier
__device__ __align__(128) unsigned int g_cnt[4 * 32];
__device__ unsigned int g_arrive;
__device__ unsigned int g_gen;

// ---------------- transpose: in[R][C] -> out[C][R] ----------------
__global__ void transpose_k(const float* __restrict__ in, float* __restrict__ out,
                            int R, int C) {
    __shared__ float tile[32][33];
    int c0 = blockIdx.x * 32, r0 = blockIdx.y * 32;
    int x = threadIdx.x, y = threadIdx.y;
#pragma unroll
    for (int j = 0; j < 32; j += 8)
        tile[y + j][x] = in[(size_t)(r0 + y + j) * C + c0 + x];
    __syncthreads();
#pragma unroll
    for (int j = 0; j < 32; j += 8)
        out[(size_t)(c0 + y + j) * R + r0 + x] = tile[x][y + j];
}

// ---------------- tiled GEMM: out[M][N] = X[M][K] @ Wt[K][N] + bias ----------------
__global__ void gemm_bias(const float* __restrict__ X, const float* __restrict__ Wt,
                          const float* __restrict__ bias, float* __restrict__ out,
                          int M, int K, int N) {
    __shared__ float As[16][64];
    __shared__ float Bs[16][64];
    int tid = threadIdx.x;
    int n0 = blockIdx.x * 64, m0 = blockIdx.y * 64;
    int tx = tid % 16, ty = tid / 16;
    int am = tid / 4, ak = (tid % 4) * 4;
    int bk = tid / 16, bn = (tid % 16) * 4;
    float acc[4][4];
#pragma unroll
    for (int i = 0; i < 4; i++)
#pragma unroll
        for (int j = 0; j < 4; j++) acc[i][j] = 0.f;

    for (int k0 = 0; k0 < K; k0 += 16) {
        float4 av = *(const float4*)&X[(size_t)(m0 + am) * K + k0 + ak];
        As[ak + 0][am] = av.x; As[ak + 1][am] = av.y;
        As[ak + 2][am] = av.z; As[ak + 3][am] = av.w;
        *(float4*)&Bs[bk][bn] = *(const float4*)&Wt[(size_t)(k0 + bk) * N + n0 + bn];
        __syncthreads();
#pragma unroll
        for (int k = 0; k < 16; k++) {
            float4 a = *(const float4*)&As[k][ty * 4];
            float4 b = *(const float4*)&Bs[k][tx * 4];
            acc[0][0] += a.x * b.x; acc[0][1] += a.x * b.y; acc[0][2] += a.x * b.z; acc[0][3] += a.x * b.w;
            acc[1][0] += a.y * b.x; acc[1][1] += a.y * b.y; acc[1][2] += a.y * b.z; acc[1][3] += a.y * b.w;
            acc[2][0] += a.z * b.x; acc[2][1] += a.z * b.y; acc[2][2] += a.z * b.z; acc[2][3] += a.z * b.w;
            acc[3][0] += a.w * b.x; acc[3][1] += a.w * b.y; acc[3][2] += a.w * b.z; acc[3][3] += a.w * b.w;
        }
        __syncthreads();
    }
    float4 bv = *(const float4*)&bias[n0 + tx * 4];
#pragma unroll
    for (int i = 0; i < 4; i++) {
        float4 o;
        o.x = acc[i][0] + bv.x; o.y = acc[i][1] + bv.y;
        o.z = acc[i][2] + bv.z; o.w = acc[i][3] + bv.w;
        *(float4*)&out[(size_t)(m0 + ty * 4 + i) * N + n0 + tx * 4] = o;
    }
}

// ---------------- sync state reset + one flat barrier for init ----------------
__global__ void bar_reset() {
    for (int i = 0; i < 4 * 32; i++) g_cnt[i] = 0u;
    g_arrive = 0u;
    g_gen = 0u;
}

__device__ __forceinline__ void grid_barrier_init() {
    __syncthreads();
    if (threadIdx.x == 0) {
        __threadfence();
        unsigned int a = atomicAdd(&g_arrive, 1u);
        if (a == NBLK - 1) {
            __threadfence();
            atomicExch(&g_gen, 1u);
        } else {
            while (*((volatile unsigned int*)&g_gen) < 1u) {}
            __threadfence();
        }
    }
    __syncthreads();
}

// ---------------- mma / async-copy helpers ----------------
__device__ __forceinline__ void mma16816(float* c, unsigned a0, unsigned a1,
                                         unsigned a2, unsigned a3,
                                         unsigned b0, unsigned b1) {
    asm volatile(
        "mma.sync.aligned.m16n8k16.row.col.f32.f16.f16.f32 "
        "{%0,%1,%2,%3}, {%4,%5,%6,%7}, {%8,%9}, {%0,%1,%2,%3};"
        : "+f"(c[0]), "+f"(c[1]), "+f"(c[2]), "+f"(c[3])
        : "r"(a0), "r"(a1), "r"(a2), "r"(a3), "r"(b0), "r"(b1));
}

__device__ __forceinline__ void ldsm4(unsigned& r0, unsigned& r1, unsigned& r2,
                                      unsigned& r3, unsigned addr) {
    asm volatile("ldmatrix.sync.aligned.m8n8.x4.shared.b16 {%0,%1,%2,%3}, [%4];"
                 : "=r"(r0), "=r"(r1), "=r"(r2), "=r"(r3) : "r"(addr));
}

__device__ __forceinline__ unsigned pack2h(__half a, __half b) {
    return (unsigned)__half_as_ushort(a) | ((unsigned)__half_as_ushort(b) << 16);
}

__device__ __forceinline__ void cpa16(unsigned dst, const void* src) {
    asm volatile("cp.async.cg.shared.global [%0], [%1], 16;" :: "r"(dst), "l"(src));
}
__device__ __forceinline__ void cpa_commit() {
    asm volatile("cp.async.commit_group;" ::: "memory");
}

__device__ __forceinline__ float fsig(float x) {
    return 1.f / (1.f + __expf(-x));
}
__device__ __forceinline__ float ftanh(float x) {
    return 2.f / (1.f + __expf(-2.f * x)) - 1.f;
}

// stage one k-chunk (128 halves of K) of the h plane: 64 rows x 256 B
__device__ __forceinline__ void stage_chunk(unsigned smem_b, const __half* shi,
                                            int c, int tid) {
#pragma unroll
    for (int u = 0; u < 4; u++) {
        int q = tid + u * 256;            // 0..1023
        int m = q >> 4, seg = q & 15;     // 64 rows x 16 segs of 16B
        cpa16(smem_b + OFF_HI + (unsigned)(m * 1040 + c * 256 + seg * 16),
              shi + m * 512 + c * 128 + seg * 8);
    }
}

// ---------------- persistent single-fp16 tensor-core GRU layer ----------------
// 128 blocks x 256 threads (8 warps). Block bid owns h-cols j0..j0+3.
// Group g = bid>>5 produces k-chunk g. Sync is pure dataflow:
// consumers wait for g_cnt[g] >= 32*t; producers bump after the gate update.
__global__ void __launch_bounds__(256, 1)
gru_layer_mma(const float* __restrict__ xg, const float* __restrict__ whh,
              const float* __restrict__ bhh, __half* __restrict__ hhi,
              float* __restrict__ y) {
    extern __shared__ unsigned char smraw[];
    float* part = (float*)(smraw + OFF_PART);
    float* own  = (float*)(smraw + OFF_OWN);
    uint2* wf   = (uint2*)(smraw + OFF_WF);
    const unsigned smem_b = (unsigned)__cvta_generic_to_shared(smraw);

    const int tid = threadIdx.x, bid = blockIdx.x;
    const int j0 = bid * 4;
    const int lane = tid & 31, wid = tid >> 5;
    const int mi = wid >> 1, ni = wid & 1;
    const int mygrp = bid >> 5;

    // ---- one-time: W_hh fragments (fp16, mma B-frag order, single plane) ----
    for (int q = tid; q < 2048; q += 256) {
        int l = q & 31, s = (q >> 5) & 31, nn = q >> 10;
        int c = nn * 8 + (l >> 2), t = l & 3;
        float e0 = 0.f, e1 = 0.f, e2 = 0.f, e3 = 0.f;
        if (c < 12) {
            int g = c >> 2, jj = c & 3;
            const float* wr = whh + (size_t)(g * Hh + j0 + jj) * Hh;
            int k = s * 16 + t * 2;
            e0 = wr[k]; e1 = wr[k + 1]; e2 = wr[k + 8]; e3 = wr[k + 9];
        }
        uint2 v;
        v.x = pack2h(__float2half_rn(e0), __float2half_rn(e1));
        v.y = pack2h(__float2half_rn(e2), __float2half_rn(e3));
        wf[q] = v;
    }

    // zero h plane slot 0 + own exact-h
    {
        int i = bid * 256 + tid;   // exactly BH chip-wide
        hhi[i] = __float2half_rn(0.f);
    }
    own[tid] = 0.f;

    // hoisted per-thread constants for the update phase
    const int ub = tid >> 2, uj = tid & 3;
    const float bhr = bhh[j0 + uj];
    const float bhz = bhh[Hh + j0 + uj];
    const float bhn = bhh[2 * Hh + j0 + uj];
    const float* xp = xg + (size_t)ub * Tt * G3 + j0 + uj;
    float* yp = y + (size_t)ub * Tt * Hh + j0 + uj;

    // ldmatrix A address; B frag address
    const unsigned aoff = (unsigned)((mi * 16 + (lane & 15)) * 1040 + (lane >> 4) * 16);
    const unsigned a_hi = smem_b + OFF_HI + aoff;
    const unsigned bbase = smem_b + OFF_WF + (unsigned)(ni * 8192 + lane * 8);

    grid_barrier_init();

    for (int t = 0; t < Tt; t++) {
        const __half* shi = hhi + (t & 1) * BH;
        __half* nhi = hhi + ((t + 1) & 1) * BH;

        // ---- dataflow wait: all 4 producer groups done with step t-1 ----
        if (tid < 4) {
            const volatile unsigned int* cp = &g_cnt[tid * 32];
            unsigned int need = 32u * (unsigned int)t;
            while (*cp < need) {}
            __threadfence();
        }
        __syncthreads();

        // prefetch xg (DRAM) for the gate phase
        float xr = xp[(size_t)t * G3];
        float xz = xp[(size_t)t * G3 + Hh];
        float xn = xp[(size_t)t * G3 + 2 * Hh];

        // ---- pipelined stage + mma over 4 k-chunks (128 halves each) ----
        float acc0[4] = {0.f, 0.f, 0.f, 0.f};
        float acc1[4] = {0.f, 0.f, 0.f, 0.f};

        stage_chunk(smem_b, shi, 0, tid);
        cpa_commit();

#pragma unroll
        for (int c = 0; c < 4; c++) {
            if (c < 3) {
                stage_chunk(smem_b, shi, c + 1, tid);
                cpa_commit();
                asm volatile("cp.async.wait_group 1;" ::: "memory");
            } else {
                asm volatile("cp.async.wait_group 0;" ::: "memory");
            }
            __syncthreads();
#pragma unroll
            for (int sl = 0; sl < 8; sl++) {
                int s = c * 8 + sl;
                unsigned A0, A1, A2, A3;
                ldsm4(A0, A1, A2, A3, a_hi + s * 32);
                unsigned b0, b1;
                asm volatile("ld.shared.v2.u32 {%0,%1}, [%2];"
                             : "=r"(b0), "=r"(b1) : "r"(bbase + s * 256));
                mma16816((sl & 1) ? acc1 : acc0, A0, A1, A2, A3, b0, b1);
            }
        }
        {
            float d0 = acc0[0] + acc1[0];
            float d1 = acc0[1] + acc1[1];
            float d2 = acc0[2] + acc1[2];
            float d3 = acc0[3] + acc1[3];
            int r = lane >> 2, tc = (lane & 3) * 2;
            int b = mi * 16 + r;
            int c0 = ni * 8 + tc;
            if (c0 < 12)     { part[b * 12 + c0]     = d0; part[(b + 8) * 12 + c0]     = d2; }
            if (c0 + 1 < 12) { part[b * 12 + c0 + 1] = d1; part[(b + 8) * 12 + c0 + 1] = d3; }
        }
        __syncthreads();

        // ---- gate update (all 256 threads: (b, j)) ----
        {
            float hr = bhr + part[ub * 12 + uj];
            float hz = bhz + part[ub * 12 + 4 + uj];
            float hn_ = bhn + part[ub * 12 + 8 + uj];
            float r = fsig(xr + hr);
            float z = fsig(xz + hz);
            float n = ftanh(xn + r * hn_);
            float hp = own[ub * 4 + uj];
            float v = (1.f - z) * n + z * hp;
            own[ub * 4 + uj] = v;
            nhi[ub * Hh + j0 + uj] = __float2half_rn(v);
            yp[(size_t)t * Hh] = v;
        }

        // ---- producer publish: no waiting ----
        __syncthreads();
        if (tid == 0) {
            __threadfence();
            atomicAdd(&g_cnt[mygrp * 32], 1u);
        }
    }
}

// ---------------- launch ----------------
extern "C" void kernel_launch(void* const* d_in, const int* in_sizes, int n_in,
                              void* d_out, int out_size) {
    const float* x     = (const float*)d_in[0];
    const float* w_ih0 = (const float*)d_in[1];
    const float* w_hh0 = (const float*)d_in[2];
    const float* b_ih0 = (const float*)d_in[3];
    const float* b_hh0 = (const float*)d_in[4];
    const float* w_ih1 = (const float*)d_in[5];
    const float* w_hh1 = (const float*)d_in[6];
    const float* b_ih1 = (const float*)d_in[7];
    const float* b_hh1 = (const float*)d_in[8];
    const float* fc_w  = (const float*)d_in[9];
    const float* fc_b  = (const float*)d_in[10];
    float* out = (float*)d_out;

    float *xg, *y, *wih0T, *wih1T, *fcwT;
    __half* hhi;
    cudaGetSymbolAddress((void**)&xg,    g_xg);
    cudaGetSymbolAddress((void**)&y,     g_y);
    cudaGetSymbolAddress((void**)&hhi,   g_hhi);
    cudaGetSymbolAddress((void**)&wih0T, g_wih0T);
    cudaGetSymbolAddress((void**)&wih1T, g_wih1T);
    cudaGetSymbolAddress((void**)&fcwT,  g_fcwT);

    cudaFuncSetAttribute(gru_layer_mma,
                         cudaFuncAttributeMaxDynamicSharedMemorySize, SMEM_TOTAL_B);

    dim3 tb(32, 8);
    transpose_k<<<dim3(Ii / 32, G3 / 32), tb>>>(w_ih0, wih0T, G3, Ii);
    transpose_k<<<dim3(Hh / 32, G3 / 32), tb>>>(w_ih1, wih1T, G3, Hh);
    transpose_k<<<dim3(Hh / 32, Ii / 32), tb>>>(fc_w,  fcwT,  Ii, Hh);

    // -------- layer 0 --------
    gemm_bias<<<dim3(G3 / 64, BT / 64), 256>>>(x, wih0T, b_ih0, xg, BT, Ii, G3);
    bar_reset<<<1, 1>>>();
    gru_layer_mma<<<NBLK, 256, SMEM_TOTAL_B>>>(xg, w_hh0, b_hh0, hhi, y);

    // -------- layer 1 --------
    gemm_bias<<<dim3(G3 / 64, BT / 64), 256>>>(y, wih1T, b_ih1, xg, BT, Hh, G3);
    bar_reset<<<1, 1>>>();
    gru_layer_mma<<<NBLK, 256, SMEM_TOTAL_B>>>(xg, w_hh1, b_hh1, hhi, y);

    // -------- final FC --------
    gemm_bias<<<dim3(Ii / 64, BT / 64), 256>>>(y, fcwT, fc_b, out, BT, Hh, Ii);
}